// round 16
// baseline (speedup 1.0000x reference)
#include <cuda_runtime.h>
#include <cuda_fp16.h>
#include <cstdint>
#include <math.h>

#define TOK   8192
#define E     1024
#define H3    3072
#define MLPD  4096
#define NHEAD 16
#define HDIM  64
#define SEQ   2048

// ---------------------------------------------------------------------------
// Scratch
// ---------------------------------------------------------------------------
__device__ uint16_t g_h   [(size_t)TOK * E];
__device__ uint16_t g_qkv [(size_t)TOK * H3];
__device__ uint16_t g_attn[(size_t)TOK * E];
__device__ float    g_x1  [(size_t)TOK * E];
__device__ uint16_t g_mlp [(size_t)TOK * MLPD];
__device__ uint16_t g_wq  [(size_t)H3 * E];
__device__ uint16_t g_wf  [(size_t)E * E];
__device__ uint16_t g_w1  [(size_t)MLPD * E];
__device__ uint16_t g_w2  [(size_t)E * MLPD];

#define QSCALE 0.18033688011112042f   // 0.125 * log2(e)

__device__ __forceinline__ uint32_t smem_u32(const void* p) {
    uint32_t a;
    asm("{ .reg .u64 t; cvta.to.shared.u64 t, %1; cvt.u32.u64 %0, t; }"
        : "=r"(a) : "l"(p));
    return a;
}

#define LDSM_X4(r, addr) \
    asm volatile("ldmatrix.sync.aligned.m8n8.x4.shared.b16 {%0,%1,%2,%3}, [%4];" \
        : "=r"((r)[0]), "=r"((r)[1]), "=r"((r)[2]), "=r"((r)[3]) : "r"(addr))

#define LDSM_X4_T(r, addr) \
    asm volatile("ldmatrix.sync.aligned.m8n8.x4.trans.shared.b16 {%0,%1,%2,%3}, [%4];" \
        : "=r"((r)[0]), "=r"((r)[1]), "=r"((r)[2]), "=r"((r)[3]) : "r"(addr))

__device__ __forceinline__ void mma_f16(float* c, const uint32_t* a, const uint32_t* b) {
    asm volatile(
        "mma.sync.aligned.m16n8k16.row.col.f32.f16.f16.f32 "
        "{%0,%1,%2,%3}, {%4,%5,%6,%7}, {%8,%9}, {%0,%1,%2,%3};"
        : "+f"(c[0]), "+f"(c[1]), "+f"(c[2]), "+f"(c[3])
        : "r"(a[0]), "r"(a[1]), "r"(a[2]), "r"(a[3]), "r"(b[0]), "r"(b[1]));
}

__device__ __forceinline__ uint32_t pack_f16(float c0, float c1) {
    uint32_t h;
    asm("cvt.rn.f16x2.f32 %0, %1, %2;" : "=r"(h) : "f"(c1), "f"(c0));
    return h;
}

__device__ __forceinline__ float ex2(float x) {
    float r;
    asm("ex2.approx.f32 %0, %1;" : "=f"(r) : "f"(x));
    return r;
}

__device__ __forceinline__ void cpa16(uint32_t dst, const void* src) {
    asm volatile("cp.async.cg.shared.global [%0], [%1], 16;"
                 :: "r"(dst), "l"(src));
}
#define CP_COMMIT() asm volatile("cp.async.commit_group;" ::: "memory")
#define CP_WAIT0()  asm volatile("cp.async.wait_group 0;" ::: "memory")
#define CP_WAIT1()  asm volatile("cp.async.wait_group 1;" ::: "memory")

// swizzled offset within a 128B-row tile
__device__ __forceinline__ uint32_t swz(uint32_t row, uint32_t col) {
    return row * 128u + (col ^ ((row & 7u) << 4));
}

// ---------------------------------------------------------------------------
// Weight pre-convert fp32 -> fp16
// ---------------------------------------------------------------------------
__global__ void wconv(const float* __restrict__ src, uint16_t* __restrict__ dst,
                      int n4)
{
    int i = blockIdx.x * 256 + threadIdx.x;
    if (i < n4) {
        float4 v = ((const float4*)src)[i];
        ((uint2*)dst)[i] = make_uint2(pack_f16(v.x, v.y), pack_f16(v.z, v.w));
    }
}

// ---------------------------------------------------------------------------
// LayerNorm: fp32 in -> fp16 out
// ---------------------------------------------------------------------------
__global__ void ln_kernel(const float* __restrict__ x,
                          const float* __restrict__ g,
                          const float* __restrict__ b,
                          uint16_t* __restrict__ y)
{
    int row = blockIdx.x;
    int tid = threadIdx.x;
    const float4* xr = (const float4*)(x + (size_t)row * E);
    float4 v = xr[tid];

    float s  = v.x + v.y + v.z + v.w;
    float ss = v.x * v.x + v.y * v.y + v.z * v.z + v.w * v.w;

    __shared__ float sbuf[32], sbuf2[32];
    #pragma unroll
    for (int o = 16; o > 0; o >>= 1) {
        s  += __shfl_down_sync(0xffffffffu, s,  o);
        ss += __shfl_down_sync(0xffffffffu, ss, o);
    }
    int warp = tid >> 5, lane = tid & 31;
    if (lane == 0) { sbuf[warp] = s; sbuf2[warp] = ss; }
    __syncthreads();
    if (warp == 0) {
        s  = lane < 8 ? sbuf[lane]  : 0.f;
        ss = lane < 8 ? sbuf2[lane] : 0.f;
        #pragma unroll
        for (int o = 4; o > 0; o >>= 1) {
            s  += __shfl_down_sync(0xffffffffu, s,  o);
            ss += __shfl_down_sync(0xffffffffu, ss, o);
        }
        if (lane == 0) { sbuf[0] = s; sbuf2[0] = ss; }
    }
    __syncthreads();
    float mean = sbuf[0] * (1.0f / E);
    float var  = sbuf2[0] * (1.0f / E) - mean * mean;
    float rstd = rsqrtf(var + 1e-5f);

    float4 gv = ((const float4*)g)[tid];
    float4 bv = ((const float4*)b)[tid];
    float o0 = (v.x - mean) * rstd * gv.x + bv.x;
    float o1 = (v.y - mean) * rstd * gv.y + bv.y;
    float o2 = (v.z - mean) * rstd * gv.z + bv.z;
    float o3 = (v.w - mean) * rstd * gv.w + bv.w;
    *(uint2*)(y + (size_t)row * E + tid * 4) =
        make_uint2(pack_f16(o0, o1), pack_f16(o2, o3));
}

// ---------------------------------------------------------------------------
// fp16 mma.sync NT GEMM, BK=64, swizzled smem, 3-stage ring. (R15, unchanged)
// ---------------------------------------------------------------------------
#define MATB   16384
#define STAGEB 32768
#define GEMM_SMEM (3 * STAGEB)

__device__ __forceinline__ void gemm_issue(uint32_t stg,
    const uint16_t* __restrict__ Ah, const uint16_t* __restrict__ Bh,
    int K, int k0, int tid)
{
    #pragma unroll
    for (int i = 0; i < 8; i++) {
        int c = i * 128 + tid;
        uint32_t r = (uint32_t)(c >> 3), kc = (uint32_t)(c & 7);
        uint32_t doff = swz(r, kc << 4);
        size_t soff = (size_t)r * K + k0 + kc * 8;
        cpa16(stg + doff,        Ah + soff);
        cpa16(stg + MATB + doff, Bh + soff);
    }
    CP_COMMIT();
}

__global__ __launch_bounds__(128, 2)
void gemm_mma(const uint16_t* __restrict__ A, const uint16_t* __restrict__ B,
              const float* __restrict__ bias, const float* __restrict__ res,
              float* __restrict__ outf, uint16_t* __restrict__ oh,
              int M, int N, int K, int act, int qcols)
{
    extern __shared__ char sm[];
    uint32_t sb = smem_u32(sm);
    int tid = threadIdx.x, w = tid >> 5, lane = tid & 31;
    int wm = w >> 1, wn = w & 1;
    int bn = blockIdx.x, bm = blockIdx.y;

    const uint16_t* Ab = A + (size_t)bm * 128 * K;
    const uint16_t* Bb = B + (size_t)bn * 128 * K;
    int nch = K >> 6;

    float acc[4][8][4];
    #pragma unroll
    for (int i = 0; i < 4; i++)
        #pragma unroll
        for (int j = 0; j < 8; j++)
            #pragma unroll
            for (int c = 0; c < 4; c++) acc[i][j][c] = 0.f;

    gemm_issue(sb, Ab, Bb, K, 0, tid);
    if (nch > 1) gemm_issue(sb + STAGEB, Ab, Bb, K, 64, tid);

    uint32_t sw_lane = (uint32_t)(lane & 7) << 4;
    uint32_t a_rowoff = (uint32_t)(wm * 64 + (lane & 15)) * 128;
    uint32_t a_col    = (uint32_t)((lane >> 4) << 4);
    uint32_t b_rowoff = (uint32_t)(wn * 64 + (lane & 7) + ((lane >> 4) & 1) * 8) * 128;
    uint32_t b_col    = (uint32_t)(((lane >> 3) & 1) << 4);

    int buf = 0;
    for (int k = 0; k < nch; k++) {
        if (k + 1 < nch) CP_WAIT1(); else CP_WAIT0();
        __syncthreads();
        if (k + 2 < nch) {
            int nb = buf + 2; if (nb >= 3) nb -= 3;
            gemm_issue(sb + (uint32_t)nb * STAGEB, Ab, Bb, K, (k + 2) * 64, tid);
        }

        uint32_t stg = sb + (uint32_t)buf * STAGEB;
        #pragma unroll
        for (int ks = 0; ks < 4; ks++) {
            uint32_t koff = (uint32_t)(ks * 32);
            uint32_t ah[4][4], bh[4][4];
            #pragma unroll
            for (int mf = 0; mf < 4; mf++)
                LDSM_X4(ah[mf], stg + a_rowoff + (uint32_t)(mf * 16) * 128
                               + ((koff | a_col) ^ sw_lane));
            #pragma unroll
            for (int np = 0; np < 4; np++)
                LDSM_X4(bh[np], stg + MATB + b_rowoff + (uint32_t)(np * 16) * 128
                               + ((koff | b_col) ^ sw_lane));
            #pragma unroll
            for (int mf = 0; mf < 4; mf++)
                #pragma unroll
                for (int nf = 0; nf < 8; nf++)
                    mma_f16(acc[mf][nf], ah[mf], &bh[nf >> 1][(nf & 1) * 2]);
        }
        if (++buf == 3) buf = 0;
    }

    int g = lane >> 2, tig = lane & 3;
    #pragma unroll
    for (int mf = 0; mf < 4; mf++) {
        #pragma unroll
        for (int h2 = 0; h2 < 2; h2++) {
            int row = bm * 128 + wm * 64 + mf * 16 + g + h2 * 8;
            size_t rb = (size_t)row * N;
            #pragma unroll
            for (int nf = 0; nf < 8; nf++) {
                int col = bn * 128 + wn * 64 + nf * 8 + tig * 2;
                float v0 = acc[mf][nf][h2 * 2 + 0];
                float v1 = acc[mf][nf][h2 * 2 + 1];
                if (bias) {
                    float2 bv = *(const float2*)(bias + col);
                    v0 += bv.x; v1 += bv.y;
                }
                if (act == 1) {
                    v0 = 0.5f * v0 * (1.0f + erff(v0 * 0.70710678118654752f));
                    v1 = 0.5f * v1 * (1.0f + erff(v1 * 0.70710678118654752f));
                }
                if (res) {
                    float2 rv = *(const float2*)(res + rb + col);
                    v0 += rv.x; v1 += rv.y;
                }
                if (outf)
                    *(float2*)(outf + rb + col) = make_float2(v0, v1);
                if (oh) {
                    float s0 = v0, s1 = v1;
                    if (col < qcols) { s0 *= QSCALE; s1 *= QSCALE; }
                    *(uint32_t*)(oh + rb + col) = pack_f16(s0, s1);
                }
            }
        }
    }
}

// ---------------------------------------------------------------------------
// fp16 flash attention: swizzled smem, 128-key double-buffered stages
// processed as two 64-key halves (registers unchanged, half the barriers).
// CTA: 128 Q rows x (head,batch). 128 threads, 2 CTAs/SM.
// smem: Q(16384), 2 stages of [K(16384) V(16384)].
// ---------------------------------------------------------------------------
#define KV0   16384
#define KVSTG 32768
#define ATTN_SMEM (KV0 + 2 * KVSTG)

__device__ __forceinline__ void attn_issue(uint32_t stg,
    const uint16_t* __restrict__ qkv, int b, int h, int kt, int tid)
{
    #pragma unroll
    for (int i = 0; i < 8; i++) {
        int c = i * 128 + tid;                // 0..1023 (128 rows x 8 granules)
        uint32_t rr = (uint32_t)(c >> 3), kc = (uint32_t)(c & 7);
        size_t base = (size_t)(b * SEQ + kt * 128 + rr) * H3 + h * HDIM + kc * 8;
        uint32_t doff = swz(rr, kc << 4);
        cpa16(stg + doff,         qkv + base + E);       // K
        cpa16(stg + 16384 + doff, qkv + base + 2 * E);   // V
    }
    CP_COMMIT();
}

__global__ __launch_bounds__(128, 2)
void attn_mma(const uint16_t* __restrict__ qkv, uint16_t* __restrict__ out)
{
    extern __shared__ char sm[];
    uint32_t sb = smem_u32(sm);
    int qt = blockIdx.x, h = blockIdx.y, b = blockIdx.z;
    int tid = threadIdx.x, w = tid >> 5, lane = tid & 31;
    int g = lane >> 2, tig = lane & 3;

    #pragma unroll
    for (int i = 0; i < 8; i++) {
        int idx = i * 128 + tid;
        uint32_t r = (uint32_t)(idx >> 3), kc = (uint32_t)(idx & 7);
        size_t t = (size_t)(b * SEQ + qt * 128 + r) * H3 + h * HDIM + kc * 8;
        cpa16(sb + swz(r, kc << 4), qkv + t);
    }
    CP_COMMIT();
    attn_issue(sb + KV0, qkv, b, h, 0, tid);
    CP_WAIT0();
    __syncthreads();

    uint32_t sw_lane = (uint32_t)(lane & 7) << 4;

    uint32_t qh[2][4][4];
    #pragma unroll
    for (int mf = 0; mf < 2; mf++) {
        uint32_t q_rowoff = (uint32_t)(w * 32 + mf * 16 + (lane & 15)) * 128;
        uint32_t q_col = (uint32_t)((lane >> 4) << 4);
        #pragma unroll
        for (int ks = 0; ks < 4; ks++)
            LDSM_X4(qh[mf][ks], sb + q_rowoff
                    + (((uint32_t)(ks * 32) | q_col) ^ sw_lane));
    }

    float o[2][8][4];
    #pragma unroll
    for (int mf = 0; mf < 2; mf++)
        #pragma unroll
        for (int nf = 0; nf < 8; nf++)
            #pragma unroll
            for (int c = 0; c < 4; c++) o[mf][nf][c] = 0.f;
    float m_[2][2] = {{-1e30f, -1e30f}, {-1e30f, -1e30f}};
    float l_[2][2] = {{0.f, 0.f}, {0.f, 0.f}};

    uint32_t kb_rowoff = (uint32_t)((lane & 7) + ((lane >> 4) & 1) * 8) * 128;
    uint32_t kb_col    = (uint32_t)(((lane >> 3) & 1) << 4);
    uint32_t vb_rowoff = (uint32_t)(lane & 15) * 128;
    uint32_t vb_col    = (uint32_t)((lane >> 4) << 4);

    for (int kt = 0; kt < SEQ / 128; kt++) {
        uint32_t stg0 = sb + KV0 + (uint32_t)(kt & 1) * KVSTG;

        if (kt + 1 < SEQ / 128)
            attn_issue(sb + KV0 + (uint32_t)((kt + 1) & 1) * KVSTG,
                       qkv, b, h, kt + 1, tid);

        #pragma unroll
        for (int half = 0; half < 2; half++) {
            uint32_t stg = stg0 + (uint32_t)half * 8192;   // 64 key-rows

            // ---- S = Q K^T ----
            float s[2][8][4];
            #pragma unroll
            for (int mf = 0; mf < 2; mf++)
                #pragma unroll
                for (int nf = 0; nf < 8; nf++)
                    #pragma unroll
                    for (int c = 0; c < 4; c++) s[mf][nf][c] = 0.f;

            #pragma unroll
            for (int ks = 0; ks < 4; ks++) {
                uint32_t koff = (uint32_t)(ks * 32);
                #pragma unroll
                for (int ng = 0; ng < 4; ng++) {
                    uint32_t kh[4];
                    LDSM_X4(kh, stg + kb_rowoff + (uint32_t)(ng * 16) * 128
                               + ((koff | kb_col) ^ sw_lane));
                    #pragma unroll
                    for (int j = 0; j < 2; j++) {
                        int nf = ng * 2 + j;
                        mma_f16(s[0][nf], qh[0][ks], &kh[j * 2]);
                        mma_f16(s[1][nf], qh[1][ks], &kh[j * 2]);
                    }
                }
            }

            // ---- online softmax (base 2) ----
            #pragma unroll
            for (int mf = 0; mf < 2; mf++)
                #pragma unroll
                for (int hh = 0; hh < 2; hh++) {
                    float mx = s[mf][0][hh * 2];
                    #pragma unroll
                    for (int nf = 0; nf < 8; nf++) {
                        mx = fmaxf(mx, s[mf][nf][hh * 2 + 0]);
                        mx = fmaxf(mx, s[mf][nf][hh * 2 + 1]);
                    }
                    mx = fmaxf(mx, __shfl_xor_sync(0xffffffffu, mx, 1));
                    mx = fmaxf(mx, __shfl_xor_sync(0xffffffffu, mx, 2));
                    float mn = fmaxf(m_[mf][hh], mx);
                    float alpha = ex2(m_[mf][hh] - mn);
                    m_[mf][hh] = mn;
                    float lsum = 0.f;
                    #pragma unroll
                    for (int nf = 0; nf < 8; nf++) {
                        float p0 = ex2(s[mf][nf][hh * 2 + 0] - mn);
                        float p1 = ex2(s[mf][nf][hh * 2 + 1] - mn);
                        s[mf][nf][hh * 2 + 0] = p0;
                        s[mf][nf][hh * 2 + 1] = p1;
                        lsum += p0 + p1;
                        o[mf][nf][hh * 2 + 0] *= alpha;
                        o[mf][nf][hh * 2 + 1] *= alpha;
                    }
                    l_[mf][hh] = l_[mf][hh] * alpha + lsum;
                }

            // ---- O += P V ----
            #pragma unroll
            for (int ks = 0; ks < 4; ks++) {
                uint32_t ph[2][4];
                #pragma unroll
                for (int mf = 0; mf < 2; mf++) {
                    ph[mf][0] = pack_f16(s[mf][ks*2  ][0], s[mf][ks*2  ][1]);
                    ph[mf][1] = pack_f16(s[mf][ks*2  ][2], s[mf][ks*2  ][3]);
                    ph[mf][2] = pack_f16(s[mf][ks*2+1][0], s[mf][ks*2+1][1]);
                    ph[mf][3] = pack_f16(s[mf][ks*2+1][2], s[mf][ks*2+1][3]);
                }
                #pragma unroll
                for (int nd = 0; nd < 4; nd++) {
                    uint32_t vh[4];
                    LDSM_X4_T(vh, stg + 16384
                              + vb_rowoff + (uint32_t)(ks * 16) * 128
                              + (((uint32_t)(nd * 32) | vb_col) ^ sw_lane));
                    #pragma unroll
                    for (int j = 0; j < 2; j++) {
                        int nf = nd * 2 + j;
                        mma_f16(o[0][nf], ph[0], &vh[j * 2]);
                        mma_f16(o[1][nf], ph[1], &vh[j * 2]);
                    }
                }
            }
        }

        CP_WAIT0();
        __syncthreads();
    }

    // ---- finalize ----
    #pragma unroll
    for (int mf = 0; mf < 2; mf++)
        #pragma unroll
        for (int hh = 0; hh < 2; hh++) {
            float lt = l_[mf][hh];
            lt += __shfl_xor_sync(0xffffffffu, lt, 1);
            lt += __shfl_xor_sync(0xffffffffu, lt, 2);
            float inv = 1.0f / lt;
            int row = qt * 128 + w * 32 + mf * 16 + g + hh * 8;
            size_t base = (size_t)(b * SEQ + row) * E + h * HDIM;
            #pragma unroll
            for (int nf = 0; nf < 8; nf++) {
                int col = nf * 8 + tig * 2;
                *(uint32_t*)(out + base + col) =
                    pack_f16(o[mf][nf][hh * 2 + 0] * inv,
                             o[mf][nf][hh * 2 + 1] * inv);
            }
        }
}

// ---------------------------------------------------------------------------
// Launch
// ---------------------------------------------------------------------------
extern "C" void kernel_launch(void* const* d_in, const int* in_sizes, int n_in,
                              void* d_out, int out_size)
{
    const float* x     = (const float*)d_in[0];
    const float* qkv_w = (const float*)d_in[1];
    const float* fc_w  = (const float*)d_in[2];
    const float* fc_b  = (const float*)d_in[3];
    const float* ln1_g = (const float*)d_in[4];
    const float* ln1_b = (const float*)d_in[5];
    const float* ln2_g = (const float*)d_in[6];
    const float* ln2_b = (const float*)d_in[7];
    const float* w1    = (const float*)d_in[8];
    const float* b1    = (const float*)d_in[9];
    const float* w2    = (const float*)d_in[10];
    const float* b2    = (const float*)d_in[11];
    float* out = (float*)d_out;

    uint16_t *ph, *pqkv, *pattn, *pmlp, *wq, *wf, *ww1, *ww2;
    float* px1;
    cudaGetSymbolAddress((void**)&ph,    g_h);
    cudaGetSymbolAddress((void**)&pqkv,  g_qkv);
    cudaGetSymbolAddress((void**)&pattn, g_attn);
    cudaGetSymbolAddress((void**)&pmlp,  g_mlp);
    cudaGetSymbolAddress((void**)&px1,   g_x1);
    cudaGetSymbolAddress((void**)&wq,    g_wq);
    cudaGetSymbolAddress((void**)&wf,    g_wf);
    cudaGetSymbolAddress((void**)&ww1,   g_w1);
    cudaGetSymbolAddress((void**)&ww2,   g_w2);

    cudaFuncSetAttribute(gemm_mma, cudaFuncAttributeMaxDynamicSharedMemorySize,
                         GEMM_SMEM);
    cudaFuncSetAttribute(attn_mma, cudaFuncAttributeMaxDynamicSharedMemorySize,
                         ATTN_SMEM);

    wconv<<<(H3 * E / 4 + 255) / 256, 256>>>(qkv_w, wq, H3 * E / 4);
    wconv<<<(E * E / 4 + 255) / 256, 256>>>(fc_w, wf, E * E / 4);
    wconv<<<(MLPD * E / 4 + 255) / 256, 256>>>(w1, ww1, MLPD * E / 4);
    wconv<<<(E * MLPD / 4 + 255) / 256, 256>>>(w2, ww2, E * MLPD / 4);

    ln_kernel<<<TOK, 256>>>(x, ln1_g, ln1_b, ph);
    gemm_mma<<<dim3(H3 / 128, TOK / 128), 128, GEMM_SMEM>>>(
        ph, wq, nullptr, nullptr, nullptr, pqkv, TOK, H3, E, 0, E);
    attn_mma<<<dim3(SEQ / 128, NHEAD, 4), 128, ATTN_SMEM>>>(pqkv, pattn);
    gemm_mma<<<dim3(E / 128, TOK / 128), 128, GEMM_SMEM>>>(
        pattn, wf, fc_b, x, px1, nullptr, TOK, E, E, 0, 0);
    ln_kernel<<<TOK, 256>>>(px1, ln2_g, ln2_b, ph);
    gemm_mma<<<dim3(MLPD / 128, TOK / 128), 128, GEMM_SMEM>>>(
        ph, ww1, b1, nullptr, nullptr, pmlp, TOK, MLPD, E, 1, 0);
    gemm_mma<<<dim3(E / 128, TOK / 128), 128, GEMM_SMEM>>>(
        pmlp, ww2, b2, px1, out, nullptr, TOK, E, MLPD, 0, 0);
}

// round 17
// speedup vs baseline: 1.0255x; 1.0255x over previous
#include <cuda_runtime.h>
#include <cuda_fp16.h>
#include <cstdint>
#include <math.h>

#define TOK   8192
#define E     1024
#define H3    3072
#define MLPD  4096
#define NHEAD 16
#define HDIM  64
#define SEQ   2048

// ---------------------------------------------------------------------------
// Scratch
// ---------------------------------------------------------------------------
__device__ uint16_t g_h   [(size_t)TOK * E];
__device__ uint16_t g_qkv [(size_t)TOK * H3];
__device__ uint16_t g_attn[(size_t)TOK * E];
__device__ float    g_x1  [(size_t)TOK * E];
__device__ uint16_t g_mlp [(size_t)TOK * MLPD];
__device__ uint16_t g_wq  [(size_t)H3 * E];
__device__ uint16_t g_wf  [(size_t)E * E];
__device__ uint16_t g_w1  [(size_t)MLPD * E];
__device__ uint16_t g_w2  [(size_t)E * MLPD];

#define QSCALE 0.18033688011112042f   // 0.125 * log2(e)

__device__ __forceinline__ uint32_t smem_u32(const void* p) {
    uint32_t a;
    asm("{ .reg .u64 t; cvta.to.shared.u64 t, %1; cvt.u32.u64 %0, t; }"
        : "=r"(a) : "l"(p));
    return a;
}

#define LDSM_X4(r, addr) \
    asm volatile("ldmatrix.sync.aligned.m8n8.x4.shared.b16 {%0,%1,%2,%3}, [%4];" \
        : "=r"((r)[0]), "=r"((r)[1]), "=r"((r)[2]), "=r"((r)[3]) : "r"(addr))

#define LDSM_X4_T(r, addr) \
    asm volatile("ldmatrix.sync.aligned.m8n8.x4.trans.shared.b16 {%0,%1,%2,%3}, [%4];" \
        : "=r"((r)[0]), "=r"((r)[1]), "=r"((r)[2]), "=r"((r)[3]) : "r"(addr))

__device__ __forceinline__ void mma_f16(float* c, const uint32_t* a, const uint32_t* b) {
    asm volatile(
        "mma.sync.aligned.m16n8k16.row.col.f32.f16.f16.f32 "
        "{%0,%1,%2,%3}, {%4,%5,%6,%7}, {%8,%9}, {%0,%1,%2,%3};"
        : "+f"(c[0]), "+f"(c[1]), "+f"(c[2]), "+f"(c[3])
        : "r"(a[0]), "r"(a[1]), "r"(a[2]), "r"(a[3]), "r"(b[0]), "r"(b[1]));
}

__device__ __forceinline__ uint32_t pack_f16(float c0, float c1) {
    uint32_t h;
    asm("cvt.rn.f16x2.f32 %0, %1, %2;" : "=r"(h) : "f"(c1), "f"(c0));
    return h;
}

__device__ __forceinline__ float ex2(float x) {
    float r;
    asm("ex2.approx.f32 %0, %1;" : "=f"(r) : "f"(x));
    return r;
}

__device__ __forceinline__ void cpa16(uint32_t dst, const void* src) {
    asm volatile("cp.async.cg.shared.global [%0], [%1], 16;"
                 :: "r"(dst), "l"(src));
}
#define CP_COMMIT() asm volatile("cp.async.commit_group;" ::: "memory")
#define CP_WAIT0()  asm volatile("cp.async.wait_group 0;" ::: "memory")
#define CP_WAIT1()  asm volatile("cp.async.wait_group 1;" ::: "memory")

// swizzled offset within a 128B-row tile
__device__ __forceinline__ uint32_t swz(uint32_t row, uint32_t col) {
    return row * 128u + (col ^ ((row & 7u) << 4));
}

// ---------------------------------------------------------------------------
// Weight pre-convert fp32 -> fp16
// ---------------------------------------------------------------------------
__global__ void wconv(const float* __restrict__ src, uint16_t* __restrict__ dst,
                      int n4)
{
    int i = blockIdx.x * 256 + threadIdx.x;
    if (i < n4) {
        float4 v = ((const float4*)src)[i];
        ((uint2*)dst)[i] = make_uint2(pack_f16(v.x, v.y), pack_f16(v.z, v.w));
    }
}

// ---------------------------------------------------------------------------
// LayerNorm: fp32 in -> fp16 out
// ---------------------------------------------------------------------------
__global__ void ln_kernel(const float* __restrict__ x,
                          const float* __restrict__ g,
                          const float* __restrict__ b,
                          uint16_t* __restrict__ y)
{
    int row = blockIdx.x;
    int tid = threadIdx.x;
    const float4* xr = (const float4*)(x + (size_t)row * E);
    float4 v = xr[tid];

    float s  = v.x + v.y + v.z + v.w;
    float ss = v.x * v.x + v.y * v.y + v.z * v.z + v.w * v.w;

    __shared__ float sbuf[32], sbuf2[32];
    #pragma unroll
    for (int o = 16; o > 0; o >>= 1) {
        s  += __shfl_down_sync(0xffffffffu, s,  o);
        ss += __shfl_down_sync(0xffffffffu, ss, o);
    }
    int warp = tid >> 5, lane = tid & 31;
    if (lane == 0) { sbuf[warp] = s; sbuf2[warp] = ss; }
    __syncthreads();
    if (warp == 0) {
        s  = lane < 8 ? sbuf[lane]  : 0.f;
        ss = lane < 8 ? sbuf2[lane] : 0.f;
        #pragma unroll
        for (int o = 4; o > 0; o >>= 1) {
            s  += __shfl_down_sync(0xffffffffu, s,  o);
            ss += __shfl_down_sync(0xffffffffu, ss, o);
        }
        if (lane == 0) { sbuf[0] = s; sbuf2[0] = ss; }
    }
    __syncthreads();
    float mean = sbuf[0] * (1.0f / E);
    float var  = sbuf2[0] * (1.0f / E) - mean * mean;
    float rstd = rsqrtf(var + 1e-5f);

    float4 gv = ((const float4*)g)[tid];
    float4 bv = ((const float4*)b)[tid];
    float o0 = (v.x - mean) * rstd * gv.x + bv.x;
    float o1 = (v.y - mean) * rstd * gv.y + bv.y;
    float o2 = (v.z - mean) * rstd * gv.z + bv.z;
    float o3 = (v.w - mean) * rstd * gv.w + bv.w;
    *(uint2*)(y + (size_t)row * E + tid * 4) =
        make_uint2(pack_f16(o0, o1), pack_f16(o2, o3));
}

// ---------------------------------------------------------------------------
// fp16 mma.sync NT GEMM, BK=64, swizzled smem, 3-stage ring. (R15, unchanged)
// ---------------------------------------------------------------------------
#define MATB   16384
#define STAGEB 32768
#define GEMM_SMEM (3 * STAGEB)

__device__ __forceinline__ void gemm_issue(uint32_t stg,
    const uint16_t* __restrict__ Ah, const uint16_t* __restrict__ Bh,
    int K, int k0, int tid)
{
    #pragma unroll
    for (int i = 0; i < 8; i++) {
        int c = i * 128 + tid;
        uint32_t r = (uint32_t)(c >> 3), kc = (uint32_t)(c & 7);
        uint32_t doff = swz(r, kc << 4);
        size_t soff = (size_t)r * K + k0 + kc * 8;
        cpa16(stg + doff,        Ah + soff);
        cpa16(stg + MATB + doff, Bh + soff);
    }
    CP_COMMIT();
}

__global__ __launch_bounds__(128, 2)
void gemm_mma(const uint16_t* __restrict__ A, const uint16_t* __restrict__ B,
              const float* __restrict__ bias, const float* __restrict__ res,
              float* __restrict__ outf, uint16_t* __restrict__ oh,
              int M, int N, int K, int act, int qcols)
{
    extern __shared__ char sm[];
    uint32_t sb = smem_u32(sm);
    int tid = threadIdx.x, w = tid >> 5, lane = tid & 31;
    int wm = w >> 1, wn = w & 1;
    int bn = blockIdx.x, bm = blockIdx.y;

    const uint16_t* Ab = A + (size_t)bm * 128 * K;
    const uint16_t* Bb = B + (size_t)bn * 128 * K;
    int nch = K >> 6;

    float acc[4][8][4];
    #pragma unroll
    for (int i = 0; i < 4; i++)
        #pragma unroll
        for (int j = 0; j < 8; j++)
            #pragma unroll
            for (int c = 0; c < 4; c++) acc[i][j][c] = 0.f;

    gemm_issue(sb, Ab, Bb, K, 0, tid);
    if (nch > 1) gemm_issue(sb + STAGEB, Ab, Bb, K, 64, tid);

    uint32_t sw_lane = (uint32_t)(lane & 7) << 4;
    uint32_t a_rowoff = (uint32_t)(wm * 64 + (lane & 15)) * 128;
    uint32_t a_col    = (uint32_t)((lane >> 4) << 4);
    uint32_t b_rowoff = (uint32_t)(wn * 64 + (lane & 7) + ((lane >> 4) & 1) * 8) * 128;
    uint32_t b_col    = (uint32_t)(((lane >> 3) & 1) << 4);

    int buf = 0;
    for (int k = 0; k < nch; k++) {
        if (k + 1 < nch) CP_WAIT1(); else CP_WAIT0();
        __syncthreads();
        if (k + 2 < nch) {
            int nb = buf + 2; if (nb >= 3) nb -= 3;
            gemm_issue(sb + (uint32_t)nb * STAGEB, Ab, Bb, K, (k + 2) * 64, tid);
        }

        uint32_t stg = sb + (uint32_t)buf * STAGEB;
        #pragma unroll
        for (int ks = 0; ks < 4; ks++) {
            uint32_t koff = (uint32_t)(ks * 32);
            uint32_t ah[4][4], bh[4][4];
            #pragma unroll
            for (int mf = 0; mf < 4; mf++)
                LDSM_X4(ah[mf], stg + a_rowoff + (uint32_t)(mf * 16) * 128
                               + ((koff | a_col) ^ sw_lane));
            #pragma unroll
            for (int np = 0; np < 4; np++)
                LDSM_X4(bh[np], stg + MATB + b_rowoff + (uint32_t)(np * 16) * 128
                               + ((koff | b_col) ^ sw_lane));
            #pragma unroll
            for (int mf = 0; mf < 4; mf++)
                #pragma unroll
                for (int nf = 0; nf < 8; nf++)
                    mma_f16(acc[mf][nf], ah[mf], &bh[nf >> 1][(nf & 1) * 2]);
        }
        if (++buf == 3) buf = 0;
    }

    int g = lane >> 2, tig = lane & 3;
    #pragma unroll
    for (int mf = 0; mf < 4; mf++) {
        #pragma unroll
        for (int h2 = 0; h2 < 2; h2++) {
            int row = bm * 128 + wm * 64 + mf * 16 + g + h2 * 8;
            size_t rb = (size_t)row * N;
            #pragma unroll
            for (int nf = 0; nf < 8; nf++) {
                int col = bn * 128 + wn * 64 + nf * 8 + tig * 2;
                float v0 = acc[mf][nf][h2 * 2 + 0];
                float v1 = acc[mf][nf][h2 * 2 + 1];
                if (bias) {
                    float2 bv = *(const float2*)(bias + col);
                    v0 += bv.x; v1 += bv.y;
                }
                if (act == 1) {
                    v0 = 0.5f * v0 * (1.0f + erff(v0 * 0.70710678118654752f));
                    v1 = 0.5f * v1 * (1.0f + erff(v1 * 0.70710678118654752f));
                }
                if (res) {
                    float2 rv = *(const float2*)(res + rb + col);
                    v0 += rv.x; v1 += rv.y;
                }
                if (outf)
                    *(float2*)(outf + rb + col) = make_float2(v0, v1);
                if (oh) {
                    float s0 = v0, s1 = v1;
                    if (col < qcols) { s0 *= QSCALE; s1 *= QSCALE; }
                    *(uint32_t*)(oh + rb + col) = pack_f16(s0, s1);
                }
            }
        }
    }
}

// ---------------------------------------------------------------------------
// fp16 flash attention: swizzled smem, 64-key tiles, 3-stage cp.async ring.
// CTA: 128 Q rows x (head,batch). 128 threads, 2 CTAs/SM.
// smem: Q(16384), 3 stages of [K(8192) V(8192)].
// ---------------------------------------------------------------------------
#define KV0   16384
#define KVSTG 16384
#define ATTN_SMEM (KV0 + 3 * KVSTG)
#define NKT   (SEQ / 64)

__device__ __forceinline__ void attn_issue(uint32_t stg,
    const uint16_t* __restrict__ qkv, int b, int h, int kt, int tid)
{
    #pragma unroll
    for (int i = 0; i < 4; i++) {
        int c = i * 128 + tid;                // 0..511 (64 rows x 8 granules)
        uint32_t rr = (uint32_t)(c >> 3), kc = (uint32_t)(c & 7);
        size_t base = (size_t)(b * SEQ + kt * 64 + rr) * H3 + h * HDIM + kc * 8;
        uint32_t doff = swz(rr, kc << 4);
        cpa16(stg + doff,        qkv + base + E);
        cpa16(stg + 8192 + doff, qkv + base + 2 * E);
    }
    CP_COMMIT();
}

__global__ __launch_bounds__(128, 2)
void attn_mma(const uint16_t* __restrict__ qkv, uint16_t* __restrict__ out)
{
    extern __shared__ char sm[];
    uint32_t sb = smem_u32(sm);
    int qt = blockIdx.x, h = blockIdx.y, b = blockIdx.z;
    int tid = threadIdx.x, w = tid >> 5, lane = tid & 31;
    int g = lane >> 2, tig = lane & 3;

    // group 1: Q tile + KV tile 0 (one commit)
    #pragma unroll
    for (int i = 0; i < 8; i++) {
        int idx = i * 128 + tid;
        uint32_t r = (uint32_t)(idx >> 3), kc = (uint32_t)(idx & 7);
        size_t t = (size_t)(b * SEQ + qt * 128 + r) * H3 + h * HDIM + kc * 8;
        cpa16(sb + swz(r, kc << 4), qkv + t);
    }
    {
        // KV tile 0 copies in the same group
        #pragma unroll
        for (int i = 0; i < 4; i++) {
            int c = i * 128 + tid;
            uint32_t rr = (uint32_t)(c >> 3), kc = (uint32_t)(c & 7);
            size_t base = (size_t)(b * SEQ + rr) * H3 + h * HDIM + kc * 8;
            uint32_t doff = swz(rr, kc << 4);
            cpa16(sb + KV0 + doff,        qkv + base + E);
            cpa16(sb + KV0 + 8192 + doff, qkv + base + 2 * E);
        }
    }
    CP_COMMIT();
    // group 2: KV tile 1
    attn_issue(sb + KV0 + KVSTG, qkv, b, h, 1, tid);

    CP_WAIT1();                 // Q + tile0 complete; tile1 may be in flight
    __syncthreads();

    uint32_t sw_lane = (uint32_t)(lane & 7) << 4;

    uint32_t qh[2][4][4];
    #pragma unroll
    for (int mf = 0; mf < 2; mf++) {
        uint32_t q_rowoff = (uint32_t)(w * 32 + mf * 16 + (lane & 15)) * 128;
        uint32_t q_col = (uint32_t)((lane >> 4) << 4);
        #pragma unroll
        for (int ks = 0; ks < 4; ks++)
            LDSM_X4(qh[mf][ks], sb + q_rowoff
                    + (((uint32_t)(ks * 32) | q_col) ^ sw_lane));
    }

    float o[2][8][4];
    #pragma unroll
    for (int mf = 0; mf < 2; mf++)
        #pragma unroll
        for (int nf = 0; nf < 8; nf++)
            #pragma unroll
            for (int c = 0; c < 4; c++) o[mf][nf][c] = 0.f;
    float m_[2][2] = {{-1e30f, -1e30f}, {-1e30f, -1e30f}};
    float l_[2][2] = {{0.f, 0.f}, {0.f, 0.f}};

    uint32_t kb_rowoff = (uint32_t)((lane & 7) + ((lane >> 4) & 1) * 8) * 128;
    uint32_t kb_col    = (uint32_t)(((lane >> 3) & 1) << 4);
    uint32_t vb_rowoff = (uint32_t)(lane & 15) * 128;
    uint32_t vb_col    = (uint32_t)((lane >> 4) << 4);

    int buf = 0;
    for (int kt = 0; kt < NKT; kt++) {
        if (kt > 0) {
            if (kt + 1 < NKT) CP_WAIT1(); else CP_WAIT0();
            __syncthreads();
        }
        if (kt + 2 < NKT) {
            int nb = buf + 2; if (nb >= 3) nb -= 3;
            attn_issue(sb + KV0 + (uint32_t)nb * KVSTG, qkv, b, h, kt + 2, tid);
        }

        uint32_t stg = sb + KV0 + (uint32_t)buf * KVSTG;

        // ---- S = Q K^T ----
        float s[2][8][4];
        #pragma unroll
        for (int mf = 0; mf < 2; mf++)
            #pragma unroll
            for (int nf = 0; nf < 8; nf++)
                #pragma unroll
                for (int c = 0; c < 4; c++) s[mf][nf][c] = 0.f;

        #pragma unroll
        for (int ks = 0; ks < 4; ks++) {
            uint32_t koff = (uint32_t)(ks * 32);
            #pragma unroll
            for (int ng = 0; ng < 4; ng++) {
                uint32_t kh[4];
                LDSM_X4(kh, stg + kb_rowoff + (uint32_t)(ng * 16) * 128
                           + ((koff | kb_col) ^ sw_lane));
                #pragma unroll
                for (int j = 0; j < 2; j++) {
                    int nf = ng * 2 + j;
                    mma_f16(s[0][nf], qh[0][ks], &kh[j * 2]);
                    mma_f16(s[1][nf], qh[1][ks], &kh[j * 2]);
                }
            }
        }

        // ---- online softmax (base 2) ----
        #pragma unroll
        for (int mf = 0; mf < 2; mf++)
            #pragma unroll
            for (int hh = 0; hh < 2; hh++) {
                float mx = s[mf][0][hh * 2];
                #pragma unroll
                for (int nf = 0; nf < 8; nf++) {
                    mx = fmaxf(mx, s[mf][nf][hh * 2 + 0]);
                    mx = fmaxf(mx, s[mf][nf][hh * 2 + 1]);
                }
                mx = fmaxf(mx, __shfl_xor_sync(0xffffffffu, mx, 1));
                mx = fmaxf(mx, __shfl_xor_sync(0xffffffffu, mx, 2));
                float mn = fmaxf(m_[mf][hh], mx);
                float alpha = ex2(m_[mf][hh] - mn);
                m_[mf][hh] = mn;
                float lsum = 0.f;
                #pragma unroll
                for (int nf = 0; nf < 8; nf++) {
                    float p0 = ex2(s[mf][nf][hh * 2 + 0] - mn);
                    float p1 = ex2(s[mf][nf][hh * 2 + 1] - mn);
                    s[mf][nf][hh * 2 + 0] = p0;
                    s[mf][nf][hh * 2 + 1] = p1;
                    lsum += p0 + p1;
                    o[mf][nf][hh * 2 + 0] *= alpha;
                    o[mf][nf][hh * 2 + 1] *= alpha;
                }
                l_[mf][hh] = l_[mf][hh] * alpha + lsum;
            }

        // ---- O += P V ----
        #pragma unroll
        for (int ks = 0; ks < 4; ks++) {
            uint32_t ph[2][4];
            #pragma unroll
            for (int mf = 0; mf < 2; mf++) {
                ph[mf][0] = pack_f16(s[mf][ks*2  ][0], s[mf][ks*2  ][1]);
                ph[mf][1] = pack_f16(s[mf][ks*2  ][2], s[mf][ks*2  ][3]);
                ph[mf][2] = pack_f16(s[mf][ks*2+1][0], s[mf][ks*2+1][1]);
                ph[mf][3] = pack_f16(s[mf][ks*2+1][2], s[mf][ks*2+1][3]);
            }
            #pragma unroll
            for (int nd = 0; nd < 4; nd++) {
                uint32_t vh[4];
                LDSM_X4_T(vh, stg + 8192
                          + vb_rowoff + (uint32_t)(ks * 16) * 128
                          + (((uint32_t)(nd * 32) | vb_col) ^ sw_lane));
                #pragma unroll
                for (int j = 0; j < 2; j++) {
                    int nf = nd * 2 + j;
                    mma_f16(o[0][nf], ph[0], &vh[j * 2]);
                    mma_f16(o[1][nf], ph[1], &vh[j * 2]);
                }
            }
        }

        if (++buf == 3) buf = 0;
    }

    // ---- finalize ----
    #pragma unroll
    for (int mf = 0; mf < 2; mf++)
        #pragma unroll
        for (int hh = 0; hh < 2; hh++) {
            float lt = l_[mf][hh];
            lt += __shfl_xor_sync(0xffffffffu, lt, 1);
            lt += __shfl_xor_sync(0xffffffffu, lt, 2);
            float inv = 1.0f / lt;
            int row = qt * 128 + w * 32 + mf * 16 + g + hh * 8;
            size_t base = (size_t)(b * SEQ + row) * E + h * HDIM;
            #pragma unroll
            for (int nf = 0; nf < 8; nf++) {
                int col = nf * 8 + tig * 2;
                *(uint32_t*)(out + base + col) =
                    pack_f16(o[mf][nf][hh * 2 + 0] * inv,
                             o[mf][nf][hh * 2 + 1] * inv);
            }
        }
}

// ---------------------------------------------------------------------------
// Launch
// ---------------------------------------------------------------------------
extern "C" void kernel_launch(void* const* d_in, const int* in_sizes, int n_in,
                              void* d_out, int out_size)
{
    const float* x     = (const float*)d_in[0];
    const float* qkv_w = (const float*)d_in[1];
    const float* fc_w  = (const float*)d_in[2];
    const float* fc_b  = (const float*)d_in[3];
    const float* ln1_g = (const float*)d_in[4];
    const float* ln1_b = (const float*)d_in[5];
    const float* ln2_g = (const float*)d_in[6];
    const float* ln2_b = (const float*)d_in[7];
    const float* w1    = (const float*)d_in[8];
    const float* b1    = (const float*)d_in[9];
    const float* w2    = (const float*)d_in[10];
    const float* b2    = (const float*)d_in[11];
    float* out = (float*)d_out;

    uint16_t *ph, *pqkv, *pattn, *pmlp, *wq, *wf, *ww1, *ww2;
    float* px1;
    cudaGetSymbolAddress((void**)&ph,    g_h);
    cudaGetSymbolAddress((void**)&pqkv,  g_qkv);
    cudaGetSymbolAddress((void**)&pattn, g_attn);
    cudaGetSymbolAddress((void**)&pmlp,  g_mlp);
    cudaGetSymbolAddress((void**)&px1,   g_x1);
    cudaGetSymbolAddress((void**)&wq,    g_wq);
    cudaGetSymbolAddress((void**)&wf,    g_wf);
    cudaGetSymbolAddress((void**)&ww1,   g_w1);
    cudaGetSymbolAddress((void**)&ww2,   g_w2);

    cudaFuncSetAttribute(gemm_mma, cudaFuncAttributeMaxDynamicSharedMemorySize,
                         GEMM_SMEM);
    cudaFuncSetAttribute(attn_mma, cudaFuncAttributeMaxDynamicSharedMemorySize,
                         ATTN_SMEM);

    wconv<<<(H3 * E / 4 + 255) / 256, 256>>>(qkv_w, wq, H3 * E / 4);
    wconv<<<(E * E / 4 + 255) / 256, 256>>>(fc_w, wf, E * E / 4);
    wconv<<<(MLPD * E / 4 + 255) / 256, 256>>>(w1, ww1, MLPD * E / 4);
    wconv<<<(E * MLPD / 4 + 255) / 256, 256>>>(w2, ww2, E * MLPD / 4);

    ln_kernel<<<TOK, 256>>>(x, ln1_g, ln1_b, ph);
    gemm_mma<<<dim3(H3 / 128, TOK / 128), 128, GEMM_SMEM>>>(
        ph, wq, nullptr, nullptr, nullptr, pqkv, TOK, H3, E, 0, E);
    attn_mma<<<dim3(SEQ / 128, NHEAD, 4), 128, ATTN_SMEM>>>(pqkv, pattn);
    gemm_mma<<<dim3(E / 128, TOK / 128), 128, GEMM_SMEM>>>(
        pattn, wf, fc_b, x, px1, nullptr, TOK, E, E, 0, 0);
    ln_kernel<<<TOK, 256>>>(px1, ln2_g, ln2_b, ph);
    gemm_mma<<<dim3(MLPD / 128, TOK / 128), 128, GEMM_SMEM>>>(
        ph, ww1, b1, nullptr, nullptr, pmlp, TOK, MLPD, E, 1, 0);
    gemm_mma<<<dim3(E / 128, TOK / 128), 128, GEMM_SMEM>>>(
        pmlp, ww2, b2, px1, out, nullptr, TOK, E, MLPD, 0, 0);
}